// round 13
// baseline (speedup 1.0000x reference)
#include <cuda_runtime.h>
#include <math.h>
#include <stdint.h>

#define Bb   4
#define SQ   2048
#define HH   8
#define DD   64
#define CIN  512
#define NHID 512
#define BH   (Bb*HH)

// ---------------- scratch (device globals; no allocation allowed) ----------
static __device__ float    g_q[(size_t)Bb*HH*SQ*DD];       // [b][h][s][d] fp32
static __device__ float    g_v[(size_t)Bb*HH*SQ*DD];       // [b][h][s][d] fp32
static __device__ uint32_t g_o16[(size_t)Bb*SQ*NHID/2];    // [b][s][h*d] fp16x2
static __device__ uint32_t g_c16[(size_t)Bb*SQ*CIN/2];     // fp16x2 c (k-pairs)
static __device__ uint32_t g_x16[(size_t)Bb*SQ*CIN/2];     // fp16x2 x
static __device__ uint32_t g_wq16[(size_t)CIN*NHID/2];     // W^T fp16x2 [n][kw]
static __device__ uint32_t g_wv16[(size_t)CIN*NHID/2];
static __device__ uint32_t g_wo16[(size_t)CIN*NHID/2];
static __device__ uint32_t g_vps[(size_t)BH*32*2048];      // packed fp16 V, S-phase
static __device__ uint32_t g_vpo[(size_t)BH*32*2048];      // packed fp16 V, PV-phase
static __device__ float    g_cos[SQ*(DD/2)];
static __device__ float    g_sin[SQ*(DD/2)];

// ---------------- helpers ----------------------------------------------------
__device__ __forceinline__ uint32_t h2pack(float lo, float hi) {
    uint32_t d; asm("cvt.rn.f16x2.f32 %0, %1, %2;" : "=r"(d) : "f"(hi), "f"(lo)); return d;
}
// fp16 m16n8k16, fp32 accum
__device__ __forceinline__ void mma16(float d[4], const uint32_t a[4], const uint32_t b[2]) {
    asm volatile("mma.sync.aligned.m16n8k16.row.col.f32.f16.f16.f32 "
                 "{%0,%1,%2,%3}, {%4,%5,%6,%7}, {%8,%9}, {%0,%1,%2,%3};\n"
                 : "+f"(d[0]), "+f"(d[1]), "+f"(d[2]), "+f"(d[3])
                 : "r"(a[0]), "r"(a[1]), "r"(a[2]), "r"(a[3]),
                   "r"(b[0]), "r"(b[1]));
}
// fp16 m16n8k16, fp16 accum (D-frag == A-frag layout)
__device__ __forceinline__ void mma16h(uint32_t d[2], const uint32_t a[4], const uint32_t b[2]) {
    asm volatile("mma.sync.aligned.m16n8k16.row.col.f16.f16.f16.f16 "
                 "{%0,%1}, {%2,%3,%4,%5}, {%6,%7}, {%0,%1};\n"
                 : "+r"(d[0]), "+r"(d[1])
                 : "r"(a[0]), "r"(a[1]), "r"(a[2]), "r"(a[3]),
                   "r"(b[0]), "r"(b[1]));
}
__device__ __forceinline__ uint32_t ex2h2(uint32_t x) {
    uint32_t y; asm("ex2.approx.f16x2 %0, %1;" : "=r"(y) : "r"(x)); return y;
}
__device__ __forceinline__ void cpa16(uint32_t saddr, const void* g) {
    asm volatile("cp.async.cg.shared.global [%0], [%1], 16;" :: "r"(saddr), "l"(g));
}
__device__ __forceinline__ void cpcommit() { asm volatile("cp.async.commit_group;"); }
__device__ __forceinline__ void cpwait0()  { asm volatile("cp.async.wait_group 0;"); }
__device__ __forceinline__ void cpwait1()  { asm volatile("cp.async.wait_group 1;"); }

// ---------------- merged prep: fp16 convert + W transpose + rope -----------
#define NC4 ((Bb*SQ*CIN)/4)
#define NWT (NHID*(CIN/2))
#define NROPE (SQ*(DD/2))
__global__ void prep_kernel(const float4* __restrict__ c, const float4* __restrict__ x,
                            const float* __restrict__ wq, const float* __restrict__ wv,
                            const float* __restrict__ wo) {
    int i = blockIdx.x * blockDim.x + threadIdx.x;
    int j = i;
    if (j < NC4) {
        float4 v = c[j];
        ((uint2*)g_c16)[j] = make_uint2(h2pack(v.x, v.y), h2pack(v.z, v.w));
        return;
    }
    j -= NC4;
    if (j < NC4) {
        float4 v = x[j];
        ((uint2*)g_x16)[j] = make_uint2(h2pack(v.x, v.y), h2pack(v.z, v.w));
        return;
    }
    j -= NC4;
    if (j < 3*NWT) {
        const float* W; uint32_t* D;
        if (j < NWT)            { W = wq; D = g_wq16; }
        else if ((j -= NWT) < NWT) { W = wv; D = g_wv16; }
        else     { j -= NWT;      W = wo; D = g_wo16; }
        int n  = j & (NHID-1);
        int kw = j >> 9;
        float a = W[(size_t)(2*kw)*NHID + n];
        float b = W[(size_t)(2*kw+1)*NHID + n];
        D[(size_t)n*(CIN/2) + kw] = h2pack(a, b);
        return;
    }
    j -= 3*NWT;
    if (j >= NROPE) return;
    int pos = j / (DD/2);
    int jj  = j % (DD/2);
    float theta = 1.0f / powf(10000.0f, (float)(2*jj) / (float)DD);
    float arg   = (float)pos * theta;
    g_cos[j] = (float)cos((double)arg);
    g_sin[j] = (float)sin((double)arg);
}

// ---------------- fp16 GEMM: 3-stage cp.async pipeline ----------------------
#define PA16 20
#define PB16 20
#define STAGE16 (128*PA16 + 64*PB16)
#define GEMM_DYN_BYTES (3*STAGE16*4)
#define NITER (CIN/32)

template<typename EPI>
__device__ __forceinline__ void gemm_body(const uint32_t* __restrict__ Aw,
                                          const uint32_t* __restrict__ Ww,
                                          int m0, int n0, EPI epi) {
    extern __shared__ uint32_t gsm[];

    int tid = threadIdx.x;
    int warp = tid >> 5, lane = tid & 31;
    int r = lane >> 2, qd = lane & 3;
    int wm = warp & 3, wn = warp >> 2;

    int rowA = tid >> 2, cA = tid & 3;
    int colB = tid >> 2, cB = tid & 3;

    auto prefetch = [&](int k0w, int s) {
        uint32_t* As = gsm + s*STAGE16;
        uint32_t* Bs = As + 128*PA16;
        #pragma unroll
        for (int t = 0; t < 2; ++t) {
            int row = rowA + t*64;
            cpa16((uint32_t)__cvta_generic_to_shared(As + row*PA16 + cA*4),
                  Aw + (size_t)(m0+row)*(CIN/2) + k0w + cA*4);
        }
        cpa16((uint32_t)__cvta_generic_to_shared(Bs + colB*PB16 + cB*4),
              Ww + (size_t)(n0+colB)*(CIN/2) + k0w + cB*4);
        cpcommit();
    };

    float acc[2][4][4];
    #pragma unroll
    for (int i = 0; i < 2; ++i)
        #pragma unroll
        for (int j = 0; j < 4; ++j)
            #pragma unroll
            for (int k = 0; k < 4; ++k) acc[i][j][k] = 0.f;

    prefetch(0, 0);
    prefetch(16, 1);

    for (int it = 0; it < NITER; ++it) {
        if (it + 1 < NITER) cpwait1(); else cpwait0();
        __syncthreads();
        if (it + 2 < NITER) prefetch((it+2)*16, (it+2)%3);

        const uint32_t* As = gsm + (it%3)*STAGE16;
        const uint32_t* Bs = As + 128*PA16;
        #pragma unroll
        for (int kc = 0; kc < 2; ++kc) {
            uint32_t a[2][4];
            #pragma unroll
            for (int mi = 0; mi < 2; ++mi) {
                int base = wm*32 + mi*16;
                a[mi][0] = As[(base + r    )*PA16 + kc*8 + qd];
                a[mi][1] = As[(base + r + 8)*PA16 + kc*8 + qd];
                a[mi][2] = As[(base + r    )*PA16 + kc*8 + 4 + qd];
                a[mi][3] = As[(base + r + 8)*PA16 + kc*8 + 4 + qd];
            }
            uint32_t b[4][2];
            #pragma unroll
            for (int ng = 0; ng < 4; ++ng) {
                int col = wn*32 + ng*8 + r;
                b[ng][0] = Bs[col*PB16 + kc*8 + qd];
                b[ng][1] = Bs[col*PB16 + kc*8 + 4 + qd];
            }
            #pragma unroll
            for (int mi = 0; mi < 2; ++mi)
                #pragma unroll
                for (int ng = 0; ng < 4; ++ng)
                    mma16(acc[mi][ng], a[mi], b[ng]);
        }
    }

    #pragma unroll
    for (int mi = 0; mi < 2; ++mi)
        #pragma unroll
        for (int rr = 0; rr < 2; ++rr) {
            int row = m0 + wm*32 + mi*16 + r + rr*8;
            #pragma unroll
            for (int ng = 0; ng < 4; ++ng) {
                int nc = n0 + wn*32 + ng*8 + 2*qd;
                epi(row, nc, acc[mi][ng][rr*2], acc[mi][ng][rr*2+1]);
            }
        }
}

__global__ void __launch_bounds__(256) proj_kernel(
        const float* __restrict__ bq, const float* __restrict__ bv) {
    const uint32_t* A = blockIdx.z ? g_x16 : g_c16;
    const uint32_t* W = blockIdx.z ? g_wv16 : g_wq16;
    const float* bias = blockIdx.z ? bv : bq;
    float* out        = blockIdx.z ? g_v : g_q;
    int m0 = blockIdx.y * 128, n0 = blockIdx.x * 64;
    gemm_body(A, W, m0, n0, [&](int row, int nc, float v0, float v1) {
        int b_ = row >> 11, s_ = row & (SQ-1);
        int h = nc >> 6, d = nc & 63;
        float* t = out + (((size_t)(b_*HH + h))*SQ + s_)*DD + d;
        t[0] = v0 + bias[nc];
        t[1] = v1 + bias[nc+1];
    });
}

__global__ void __launch_bounds__(256) outproj_kernel(
        const float* __restrict__ bo,
        const float* __restrict__ res, float* __restrict__ outbuf) {
    int m0 = blockIdx.y * 128, n0 = blockIdx.x * 64;
    gemm_body((const uint32_t*)g_o16, (const uint32_t*)g_wo16, m0, n0,
              [&](int row, int nc, float v0, float v1) {
        size_t o = (size_t)row*CIN + nc;
        outbuf[o]   = v0 + bo[nc]   + res[o];
        outbuf[o+1] = v1 + bo[nc+1] + res[o+1];
    });
}

// ---------------- V pre-pack: fp16 fragment-order layouts ------------------
__global__ void __launch_bounds__(256) packv_kernel() {
    __shared__ uint32_t Vh[64*33];
    __shared__ uint32_t Ps[2048];
    __shared__ uint32_t Po[2048];
    int jt = blockIdx.x, bh = blockIdx.y;
    const float4* Vg = (const float4*)(g_v + ((size_t)bh*SQ + jt*64)*DD);
    int tid = threadIdx.x;

    #pragma unroll
    for (int t = 0; t < 4; ++t) {
        int idx = tid + t*256;
        float4 v4 = Vg[idx];
        int j = idx >> 4, d = (idx & 15) << 2;
        Vh[j*33 + (d>>1)]     = h2pack(v4.x, v4.y);
        Vh[j*33 + (d>>1) + 1] = h2pack(v4.z, v4.w);
    }
    __syncthreads();

    #pragma unroll
    for (int t = 0; t < 8; ++t) {
        int i = tid + t*256;
        int g = i >> 6, li = i & 63;
        int lane = li >> 1, slot = li & 1;
        int r = lane >> 2, qd = lane & 3;
        {
            int nt = g >> 2, kc = g & 3;
            Ps[i] = Vh[(nt*8 + r)*33 + kc*8 + slot*4 + qd];
        }
        {
            int kt = g >> 3, dg = g & 7;
            int j0 = kt*16 + slot*8 + 2*qd;
            int d  = dg*8 + r;
            uint32_t w0 = Vh[ j0   *33 + (d>>1)];
            uint32_t w1 = Vh[(j0+1)*33 + (d>>1)];
            uint32_t lo = (d & 1) ? (w0 >> 16) : (w0 & 0xffffu);
            uint32_t hi = (d & 1) ? (w1 >> 16) : (w1 & 0xffffu);
            Po[i] = lo | (hi << 16);
        }
    }
    __syncthreads();

    uint4* dstS = (uint4*)(g_vps + ((size_t)bh*32 + jt)*2048);
    uint4* dstO = (uint4*)(g_vpo + ((size_t)bh*32 + jt)*2048);
    #pragma unroll
    for (int t = 0; t < 2; ++t) {
        int i = tid + t*256;
        dstS[i] = *(const uint4*)(Ps + i*4);
        dstO[i] = *(const uint4*)(Po + i*4);
    }
}

// ---------------- fused flash attention (fp16 accum softmax path) ----------
#define FL_STAGE 4096
#define FLASH_DYN_BYTES (2*FL_STAGE*4)         // 32 KB
#define NTILES (SQ/64)                         // 32

__global__ void __launch_bounds__(256, 2) flash_kernel() {
    extern __shared__ uint32_t fsm[];

    int bh = blockIdx.y;
    int i0 = blockIdx.x * 128;
    const float* Qg = g_q + (size_t)bh*SQ*DD;
    const uint32_t* SrcS = g_vps + (size_t)bh*32*2048;
    const uint32_t* SrcO = g_vpo + (size_t)bh*32*2048;

    int tid = threadIdx.x;
    int w = tid >> 5, lane = tid & 31;
    int r = lane >> 2, qd = lane & 3;
    int row0 = w*16 + r;

    auto prefetchV = [&](int jt, int s) {
        uint32_t* dst = fsm + s*FL_STAGE;
        const uint32_t* ss = SrcS + (size_t)jt*2048;
        const uint32_t* so = SrcO + (size_t)jt*2048;
        #pragma unroll
        for (int t = 0; t < 2; ++t) {
            int ch = tid + t*256;
            cpa16((uint32_t)__cvta_generic_to_shared(dst + ch*4),        ss + ch*4);
            cpa16((uint32_t)__cvta_generic_to_shared(dst + 2048 + ch*4), so + ch*4);
        }
        cpcommit();
    };

    // Q fragments (fp16): rope + scale*log2e fused.
    const float QSC = 0.125f * 1.4426950408889634f;
    uint32_t qf[4][4];
    {
        int s0 = i0 + row0, s1 = s0 + 8;
        const float* Q0 = Qg + (size_t)s0*DD;
        const float* Q1 = Qg + (size_t)s1*DD;
        const float* c0 = g_cos + (size_t)s0*(DD/2);
        const float* sn0 = g_sin + (size_t)s0*(DD/2);
        const float* c1 = g_cos + (size_t)s1*(DD/2);
        const float* sn1 = g_sin + (size_t)s1*(DD/2);
        int off[4] = { 2*qd, 2*qd+1, 8+2*qd, 9+2*qd };
        #pragma unroll
        for (int kc2 = 0; kc2 < 2; ++kc2) {
            float lo0[4], hi0[4], lo1[4], hi1[4];
            #pragma unroll
            for (int oi = 0; oi < 4; ++oi) {
                int d = kc2*16 + off[oi];
                float x1 = Q0[d], x2 = Q0[d+32];
                float cc = c0[d], sn = sn0[d];
                lo0[oi] = (x1*cc - x2*sn) * QSC;
                hi0[oi] = (x2*cc + x1*sn) * QSC;
                float y1 = Q1[d], y2 = Q1[d+32];
                float dc = c1[d], dn = sn1[d];
                lo1[oi] = (y1*dc - y2*dn) * QSC;
                hi1[oi] = (y2*dc + y1*dn) * QSC;
            }
            qf[kc2][0]   = h2pack(lo0[0], lo0[1]);
            qf[kc2][1]   = h2pack(lo1[0], lo1[1]);
            qf[kc2][2]   = h2pack(lo0[2], lo0[3]);
            qf[kc2][3]   = h2pack(lo1[2], lo1[3]);
            qf[kc2+2][0] = h2pack(hi0[0], hi0[1]);
            qf[kc2+2][1] = h2pack(hi1[0], hi1[1]);
            qf[kc2+2][2] = h2pack(hi0[2], hi0[3]);
            qf[kc2+2][3] = h2pack(hi1[2], hi1[3]);
        }
    }

    float oacc[8][4];
    #pragma unroll
    for (int i = 0; i < 8; ++i)
        #pragma unroll
        for (int j = 0; j < 4; ++j) oacc[i][j] = 0.f;
    float lsum[4] = {0.f, 0.f, 0.f, 0.f};          // ones-column row sums (fp32)
    const uint32_t ONES2 = 0x3C003C00u;            // (1.0h, 1.0h)
    const uint32_t bones[2] = { ONES2, ONES2 };

    prefetchV(0, 0);

    for (int jt = 0; jt < NTILES; ++jt) {
        cpwait0();
        __syncthreads();
        if (jt + 1 < NTILES) prefetchV(jt+1, (jt+1)&1);

        const uint32_t* VpS = fsm + (jt&1)*FL_STAGE;
        const uint32_t* VpO = VpS + 2048;

        // S = (Q*scale*log2e) @ V^T  — fp16 accumulators (D-frag == A-frag)
        uint32_t sacc[8][2];
        #pragma unroll
        for (int i = 0; i < 8; ++i) { sacc[i][0] = 0u; sacc[i][1] = 0u; }
        #pragma unroll
        for (int kc = 0; kc < 4; ++kc) {
            #pragma unroll
            for (int nt = 0; nt < 8; ++nt) {
                uint2 bb = *(const uint2*)(VpS + (nt*4 + kc)*64 + lane*2);
                uint32_t b[2] = {bb.x, bb.y};
                mma16h(sacc[nt], qf[kc], b);
            }
        }

        // P = 2^S, packed (no max subtraction: logits bounded)
        #pragma unroll
        for (int nt = 0; nt < 8; ++nt) {
            sacc[nt][0] = ex2h2(sacc[nt][0]);
            sacc[nt][1] = ex2h2(sacc[nt][1]);
        }

        // O += P @ V ; row sums via all-ones B column (exact fp32 accum)
        #pragma unroll
        for (int kt = 0; kt < 4; ++kt) {
            uint32_t pa[4] = { sacc[2*kt][0], sacc[2*kt][1],
                               sacc[2*kt+1][0], sacc[2*kt+1][1] };
            mma16(lsum, pa, bones);
            #pragma unroll
            for (int dg = 0; dg < 8; ++dg) {
                uint2 bb = *(const uint2*)(VpO + (kt*8 + dg)*64 + lane*2);
                uint32_t b[2] = {bb.x, bb.y};
                mma16(oacc[dg], pa, b);
            }
        }
    }

    // ---- normalize + write O as fp16x2 ----
    int b_ = bh >> 3, h = bh & 7;
    float inv0 = 1.0f / lsum[0], inv1 = 1.0f / lsum[2];
    uint32_t* O0 = g_o16 + (((size_t)b_*SQ + (i0 + row0))*NHID + h*DD)/2;
    uint32_t* O1 = O0 + (size_t)8*(NHID/2);
    #pragma unroll
    for (int dg = 0; dg < 8; ++dg) {
        int wi = dg*4 + qd;
        O0[wi] = h2pack(oacc[dg][0]*inv0, oacc[dg][1]*inv0);
        O1[wi] = h2pack(oacc[dg][2]*inv1, oacc[dg][3]*inv1);
    }
}

// ---------------- launcher ---------------------------------------------------
extern "C" void kernel_launch(void* const* d_in, const int* in_sizes, int n_in,
                              void* d_out, int out_size) {
    const float* x  = (const float*)d_in[0];
    const float* c  = (const float*)d_in[1];
    // d_in[2..3] = Wq, bq ; d_in[4..5] = Wk, bk (UNUSED by reference) ;
    // d_in[6..7] = Wv, bv ; d_in[8..9] = Wo, bo
    const float* Wq = (const float*)d_in[2];
    const float* bq = (const float*)d_in[3];
    const float* Wv = (const float*)d_in[6];
    const float* bv = (const float*)d_in[7];
    const float* Wo = (const float*)d_in[8];
    const float* bo = (const float*)d_in[9];
    float* out = (float*)d_out;

    cudaFuncSetAttribute(proj_kernel, cudaFuncAttributeMaxDynamicSharedMemorySize,
                         GEMM_DYN_BYTES);
    cudaFuncSetAttribute(outproj_kernel, cudaFuncAttributeMaxDynamicSharedMemorySize,
                         GEMM_DYN_BYTES);
    cudaFuncSetAttribute(flash_kernel, cudaFuncAttributeMaxDynamicSharedMemorySize,
                         FLASH_DYN_BYTES);

    int prep_total = 2*NC4 + 3*NWT + NROPE;
    prep_kernel<<<(prep_total + 255)/256, 256>>>(
        (const float4*)c, (const float4*)x, Wq, Wv, Wo);
    proj_kernel<<<dim3(NHID/64, (Bb*SQ)/128, 2), 256, GEMM_DYN_BYTES>>>(bq, bv);
    packv_kernel<<<dim3(32, BH), 256>>>();
    flash_kernel<<<dim3(SQ/128, BH), 256, FLASH_DYN_BYTES>>>();
    outproj_kernel<<<dim3(CIN/64, (Bb*SQ)/128), 256, GEMM_DYN_BYTES>>>(bo, x, out);
}

// round 14
// speedup vs baseline: 1.0078x; 1.0078x over previous
#include <cuda_runtime.h>
#include <math.h>
#include <stdint.h>

#define Bb   4
#define SQ   2048
#define HH   8
#define DD   64
#define CIN  512
#define NHID 512
#define BH   (Bb*HH)

// ---------------- scratch (device globals; no allocation allowed) ----------
static __device__ float    g_q[(size_t)Bb*HH*SQ*DD];       // [b][h][s][d] fp32
static __device__ float    g_v[(size_t)Bb*HH*SQ*DD];       // [b][h][s][d] fp32
static __device__ uint32_t g_o16[(size_t)Bb*SQ*NHID/2];    // [b][s][h*d] fp16x2
static __device__ uint32_t g_c16[(size_t)Bb*SQ*CIN/2];     // fp16x2 c (k-pairs)
static __device__ uint32_t g_x16[(size_t)Bb*SQ*CIN/2];     // fp16x2 x
static __device__ uint32_t g_wq16[(size_t)CIN*NHID/2];     // W^T fp16x2 [n][kw]
static __device__ uint32_t g_wv16[(size_t)CIN*NHID/2];
static __device__ uint32_t g_wo16[(size_t)CIN*NHID/2];
static __device__ uint32_t g_vps[(size_t)BH*32*2048];      // packed fp16 V, S-phase
static __device__ uint32_t g_vpo[(size_t)BH*32*2048];      // packed fp16 V, PV-phase
static __device__ float    g_cos[SQ*(DD/2)];
static __device__ float    g_sin[SQ*(DD/2)];

// ---------------- helpers ----------------------------------------------------
__device__ __forceinline__ uint32_t h2pack(float lo, float hi) {
    uint32_t d; asm("cvt.rn.f16x2.f32 %0, %1, %2;" : "=r"(d) : "f"(hi), "f"(lo)); return d;
}
__device__ __forceinline__ void mma16(float d[4], const uint32_t a[4], const uint32_t b[2]) {
    asm volatile("mma.sync.aligned.m16n8k16.row.col.f32.f16.f16.f32 "
                 "{%0,%1,%2,%3}, {%4,%5,%6,%7}, {%8,%9}, {%0,%1,%2,%3};\n"
                 : "+f"(d[0]), "+f"(d[1]), "+f"(d[2]), "+f"(d[3])
                 : "r"(a[0]), "r"(a[1]), "r"(a[2]), "r"(a[3]),
                   "r"(b[0]), "r"(b[1]));
}
__device__ __forceinline__ void mma16h(uint32_t d[2], const uint32_t a[4], const uint32_t b[2]) {
    asm volatile("mma.sync.aligned.m16n8k16.row.col.f16.f16.f16.f16 "
                 "{%0,%1}, {%2,%3,%4,%5}, {%6,%7}, {%0,%1};\n"
                 : "+r"(d[0]), "+r"(d[1])
                 : "r"(a[0]), "r"(a[1]), "r"(a[2]), "r"(a[3]),
                   "r"(b[0]), "r"(b[1]));
}
__device__ __forceinline__ uint32_t ex2h2(uint32_t x) {
    uint32_t y; asm("ex2.approx.f16x2 %0, %1;" : "=r"(y) : "r"(x)); return y;
}
__device__ __forceinline__ void cpa16(uint32_t saddr, const void* g) {
    asm volatile("cp.async.cg.shared.global [%0], [%1], 16;" :: "r"(saddr), "l"(g));
}
__device__ __forceinline__ void cpcommit() { asm volatile("cp.async.commit_group;"); }
__device__ __forceinline__ void cpwait0()  { asm volatile("cp.async.wait_group 0;"); }
__device__ __forceinline__ void cpwait1()  { asm volatile("cp.async.wait_group 1;"); }
__device__ __forceinline__ void cpwait2()  { asm volatile("cp.async.wait_group 2;"); }
__device__ __forceinline__ void cpwait3()  { asm volatile("cp.async.wait_group 3;"); }

// ---------------- merged prep: fp16 convert + W transpose + rope -----------
#define NC4 ((Bb*SQ*CIN)/4)
#define NWT (NHID*(CIN/2))
#define NROPE (SQ*(DD/2))
__global__ void prep_kernel(const float4* __restrict__ c, const float4* __restrict__ x,
                            const float* __restrict__ wq, const float* __restrict__ wv,
                            const float* __restrict__ wo) {
    int i = blockIdx.x * blockDim.x + threadIdx.x;
    int j = i;
    if (j < NC4) {
        float4 v = c[j];
        ((uint2*)g_c16)[j] = make_uint2(h2pack(v.x, v.y), h2pack(v.z, v.w));
        return;
    }
    j -= NC4;
    if (j < NC4) {
        float4 v = x[j];
        ((uint2*)g_x16)[j] = make_uint2(h2pack(v.x, v.y), h2pack(v.z, v.w));
        return;
    }
    j -= NC4;
    if (j < 3*NWT) {
        const float* W; uint32_t* D;
        if (j < NWT)            { W = wq; D = g_wq16; }
        else if ((j -= NWT) < NWT) { W = wv; D = g_wv16; }
        else     { j -= NWT;      W = wo; D = g_wo16; }
        int n  = j & (NHID-1);
        int kw = j >> 9;
        float a = W[(size_t)(2*kw)*NHID + n];
        float b = W[(size_t)(2*kw+1)*NHID + n];
        D[(size_t)n*(CIN/2) + kw] = h2pack(a, b);
        return;
    }
    j -= 3*NWT;
    if (j >= NROPE) return;
    int pos = j / (DD/2);
    int jj  = j % (DD/2);
    float theta = 1.0f / powf(10000.0f, (float)(2*jj) / (float)DD);
    float arg   = (float)pos * theta;
    g_cos[j] = (float)cos((double)arg);
    g_sin[j] = (float)sin((double)arg);
}

// ---------------- fp16 GEMM: 3-stage cp.async pipeline ----------------------
#define PA16 20
#define PB16 20
#define STAGE16 (128*PA16 + 64*PB16)
#define GEMM_DYN_BYTES (3*STAGE16*4)
#define NITER (CIN/32)

template<typename EPI>
__device__ __forceinline__ void gemm_body(const uint32_t* __restrict__ Aw,
                                          const uint32_t* __restrict__ Ww,
                                          int m0, int n0, EPI epi) {
    extern __shared__ uint32_t gsm[];

    int tid = threadIdx.x;
    int warp = tid >> 5, lane = tid & 31;
    int r = lane >> 2, qd = lane & 3;
    int wm = warp & 3, wn = warp >> 2;

    int rowA = tid >> 2, cA = tid & 3;
    int colB = tid >> 2, cB = tid & 3;

    auto prefetch = [&](int k0w, int s) {
        uint32_t* As = gsm + s*STAGE16;
        uint32_t* Bs = As + 128*PA16;
        #pragma unroll
        for (int t = 0; t < 2; ++t) {
            int row = rowA + t*64;
            cpa16((uint32_t)__cvta_generic_to_shared(As + row*PA16 + cA*4),
                  Aw + (size_t)(m0+row)*(CIN/2) + k0w + cA*4);
        }
        cpa16((uint32_t)__cvta_generic_to_shared(Bs + colB*PB16 + cB*4),
              Ww + (size_t)(n0+colB)*(CIN/2) + k0w + cB*4);
        cpcommit();
    };

    float acc[2][4][4];
    #pragma unroll
    for (int i = 0; i < 2; ++i)
        #pragma unroll
        for (int j = 0; j < 4; ++j)
            #pragma unroll
            for (int k = 0; k < 4; ++k) acc[i][j][k] = 0.f;

    prefetch(0, 0);
    prefetch(16, 1);

    for (int it = 0; it < NITER; ++it) {
        if (it + 1 < NITER) cpwait1(); else cpwait0();
        __syncthreads();
        if (it + 2 < NITER) prefetch((it+2)*16, (it+2)%3);

        const uint32_t* As = gsm + (it%3)*STAGE16;
        const uint32_t* Bs = As + 128*PA16;
        #pragma unroll
        for (int kc = 0; kc < 2; ++kc) {
            uint32_t a[2][4];
            #pragma unroll
            for (int mi = 0; mi < 2; ++mi) {
                int base = wm*32 + mi*16;
                a[mi][0] = As[(base + r    )*PA16 + kc*8 + qd];
                a[mi][1] = As[(base + r + 8)*PA16 + kc*8 + qd];
                a[mi][2] = As[(base + r    )*PA16 + kc*8 + 4 + qd];
                a[mi][3] = As[(base + r + 8)*PA16 + kc*8 + 4 + qd];
            }
            uint32_t b[4][2];
            #pragma unroll
            for (int ng = 0; ng < 4; ++ng) {
                int col = wn*32 + ng*8 + r;
                b[ng][0] = Bs[col*PB16 + kc*8 + qd];
                b[ng][1] = Bs[col*PB16 + kc*8 + 4 + qd];
            }
            #pragma unroll
            for (int mi = 0; mi < 2; ++mi)
                #pragma unroll
                for (int ng = 0; ng < 4; ++ng)
                    mma16(acc[mi][ng], a[mi], b[ng]);
        }
    }

    #pragma unroll
    for (int mi = 0; mi < 2; ++mi)
        #pragma unroll
        for (int rr = 0; rr < 2; ++rr) {
            int row = m0 + wm*32 + mi*16 + r + rr*8;
            #pragma unroll
            for (int ng = 0; ng < 4; ++ng) {
                int nc = n0 + wn*32 + ng*8 + 2*qd;
                epi(row, nc, acc[mi][ng][rr*2], acc[mi][ng][rr*2+1]);
            }
        }
}

__global__ void __launch_bounds__(256) proj_kernel(
        const float* __restrict__ bq, const float* __restrict__ bv) {
    const uint32_t* A = blockIdx.z ? g_x16 : g_c16;
    const uint32_t* W = blockIdx.z ? g_wv16 : g_wq16;
    const float* bias = blockIdx.z ? bv : bq;
    float* out        = blockIdx.z ? g_v : g_q;
    int m0 = blockIdx.y * 128, n0 = blockIdx.x * 64;
    gemm_body(A, W, m0, n0, [&](int row, int nc, float v0, float v1) {
        int b_ = row >> 11, s_ = row & (SQ-1);
        int h = nc >> 6, d = nc & 63;
        float* t = out + (((size_t)(b_*HH + h))*SQ + s_)*DD + d;
        t[0] = v0 + bias[nc];
        t[1] = v1 + bias[nc+1];
    });
}

__global__ void __launch_bounds__(256) outproj_kernel(
        const float* __restrict__ bo,
        const float* __restrict__ res, float* __restrict__ outbuf) {
    int m0 = blockIdx.y * 128, n0 = blockIdx.x * 64;
    gemm_body((const uint32_t*)g_o16, (const uint32_t*)g_wo16, m0, n0,
              [&](int row, int nc, float v0, float v1) {
        size_t o = (size_t)row*CIN + nc;
        outbuf[o]   = v0 + bo[nc]   + res[o];
        outbuf[o+1] = v1 + bo[nc+1] + res[o+1];
    });
}

// ---------------- V pre-pack: fp16 fragment-order layouts ------------------
__global__ void __launch_bounds__(256) packv_kernel() {
    __shared__ uint32_t Vh[64*33];
    __shared__ uint32_t Ps[2048];
    __shared__ uint32_t Po[2048];
    int jt = blockIdx.x, bh = blockIdx.y;
    const float4* Vg = (const float4*)(g_v + ((size_t)bh*SQ + jt*64)*DD);
    int tid = threadIdx.x;

    #pragma unroll
    for (int t = 0; t < 4; ++t) {
        int idx = tid + t*256;
        float4 v4 = Vg[idx];
        int j = idx >> 4, d = (idx & 15) << 2;
        Vh[j*33 + (d>>1)]     = h2pack(v4.x, v4.y);
        Vh[j*33 + (d>>1) + 1] = h2pack(v4.z, v4.w);
    }
    __syncthreads();

    #pragma unroll
    for (int t = 0; t < 8; ++t) {
        int i = tid + t*256;
        int g = i >> 6, li = i & 63;
        int lane = li >> 1, slot = li & 1;
        int r = lane >> 2, qd = lane & 3;
        {
            int nt = g >> 2, kc = g & 3;
            Ps[i] = Vh[(nt*8 + r)*33 + kc*8 + slot*4 + qd];
        }
        {
            int kt = g >> 3, dg = g & 7;
            int j0 = kt*16 + slot*8 + 2*qd;
            int d  = dg*8 + r;
            uint32_t w0 = Vh[ j0   *33 + (d>>1)];
            uint32_t w1 = Vh[(j0+1)*33 + (d>>1)];
            uint32_t lo = (d & 1) ? (w0 >> 16) : (w0 & 0xffffu);
            uint32_t hi = (d & 1) ? (w1 >> 16) : (w1 & 0xffffu);
            Po[i] = lo | (hi << 16);
        }
    }
    __syncthreads();

    uint4* dstS = (uint4*)(g_vps + ((size_t)bh*32 + jt)*2048);
    uint4* dstO = (uint4*)(g_vpo + ((size_t)bh*32 + jt)*2048);
    #pragma unroll
    for (int t = 0; t < 2; ++t) {
        int i = tid + t*256;
        dstS[i] = *(const uint4*)(Ps + i*4);
        dstO[i] = *(const uint4*)(Po + i*4);
    }
}

// ---------------- fused flash attention: cross-tile software pipeline ------
#define NSTG 5
#define FL_STAGE 4096
#define FLASH_DYN_BYTES (NSTG*FL_STAGE*4)      // 80 KB
#define NTILES (SQ/64)                         // 32

__global__ void __launch_bounds__(256, 2) flash_kernel() {
    extern __shared__ uint32_t fsm[];

    int bh = blockIdx.y;
    int i0 = blockIdx.x * 128;
    const float* Qg = g_q + (size_t)bh*SQ*DD;
    const uint32_t* SrcS = g_vps + (size_t)bh*32*2048;
    const uint32_t* SrcO = g_vpo + (size_t)bh*32*2048;

    int tid = threadIdx.x;
    int lane = tid & 31;
    int r = lane >> 2, qd = lane & 3;
    int row0 = (tid >> 5)*16 + r;

    auto prefetchV = [&](int jt, int s) {
        uint32_t* dst = fsm + s*FL_STAGE;
        const uint32_t* ss = SrcS + (size_t)jt*2048;
        const uint32_t* so = SrcO + (size_t)jt*2048;
        #pragma unroll
        for (int t = 0; t < 2; ++t) {
            int ch = tid + t*256;
            cpa16((uint32_t)__cvta_generic_to_shared(dst + ch*4),        ss + ch*4);
            cpa16((uint32_t)__cvta_generic_to_shared(dst + 2048 + ch*4), so + ch*4);
        }
        cpcommit();
    };

    // Q fragments (fp16): rope + scale*log2e fused.
    const float QSC = 0.125f * 1.4426950408889634f;
    uint32_t qf[4][4];
    {
        int s0 = i0 + row0, s1 = s0 + 8;
        const float* Q0 = Qg + (size_t)s0*DD;
        const float* Q1 = Qg + (size_t)s1*DD;
        const float* c0 = g_cos + (size_t)s0*(DD/2);
        const float* sn0 = g_sin + (size_t)s0*(DD/2);
        const float* c1 = g_cos + (size_t)s1*(DD/2);
        const float* sn1 = g_sin + (size_t)s1*(DD/2);
        int off[4] = { 2*qd, 2*qd+1, 8+2*qd, 9+2*qd };
        #pragma unroll
        for (int kc2 = 0; kc2 < 2; ++kc2) {
            float lo0[4], hi0[4], lo1[4], hi1[4];
            #pragma unroll
            for (int oi = 0; oi < 4; ++oi) {
                int d = kc2*16 + off[oi];
                float x1 = Q0[d], x2 = Q0[d+32];
                float cc = c0[d], sn = sn0[d];
                lo0[oi] = (x1*cc - x2*sn) * QSC;
                hi0[oi] = (x2*cc + x1*sn) * QSC;
                float y1 = Q1[d], y2 = Q1[d+32];
                float dc = c1[d], dn = sn1[d];
                lo1[oi] = (y1*dc - y2*dn) * QSC;
                hi1[oi] = (y2*dc + y1*dn) * QSC;
            }
            qf[kc2][0]   = h2pack(lo0[0], lo0[1]);
            qf[kc2][1]   = h2pack(lo1[0], lo1[1]);
            qf[kc2][2]   = h2pack(lo0[2], lo0[3]);
            qf[kc2][3]   = h2pack(lo1[2], lo1[3]);
            qf[kc2+2][0] = h2pack(hi0[0], hi0[1]);
            qf[kc2+2][1] = h2pack(hi1[0], hi1[1]);
            qf[kc2+2][2] = h2pack(hi0[2], hi0[3]);
            qf[kc2+2][3] = h2pack(hi1[2], hi1[3]);
        }
    }

    float oacc[8][4];
    #pragma unroll
    for (int i = 0; i < 8; ++i)
        #pragma unroll
        for (int j = 0; j < 4; ++j) oacc[i][j] = 0.f;
    float lsum[4] = {0.f, 0.f, 0.f, 0.f};
    const uint32_t ONES2 = 0x3C003C00u;
    const uint32_t bones[2] = { ONES2, ONES2 };

    // double-buffered probability fragments (D-frag == A-frag)
    uint32_t sacc[2][8][2];

    // ---- prologue: fill 4 of 5 stages; compute S_0 ----
    prefetchV(0, 0); prefetchV(1, 1); prefetchV(2, 2); prefetchV(3, 3);
    cpwait3();
    __syncthreads();
    {
        const uint32_t* VpS = fsm;            // stage 0
        #pragma unroll
        for (int i = 0; i < 8; ++i) { sacc[0][i][0] = 0u; sacc[0][i][1] = 0u; }
        #pragma unroll
        for (int kc = 0; kc < 4; ++kc)
            #pragma unroll
            for (int nt = 0; nt < 8; ++nt) {
                uint2 bb = *(const uint2*)(VpS + (nt*4 + kc)*64 + lane*2);
                uint32_t b[2] = {bb.x, bb.y};
                mma16h(sacc[0][nt], qf[kc], b);
            }
        #pragma unroll
        for (int nt = 0; nt < 8; ++nt) {
            sacc[0][nt][0] = ex2h2(sacc[0][nt][0]);
            sacc[0][nt][1] = ex2h2(sacc[0][nt][1]);
        }
    }

    // ---- main pipeline: per iter — wait/sync, prefetch jt+4, S_{jt+1}, PV_jt
    int st_cur = 0, st_next = 1, st_pf = 4;
    #pragma unroll 2
    for (int jt = 0; jt < NTILES; ++jt) {
        int cur = jt & 1;
        if (jt + 1 < NTILES) {
            cpwait2();                         // tile jt+1 copies complete
            __syncthreads();                   // visible to all; all past PV_{jt-1}
            if (jt + 4 < NTILES) prefetchV(jt + 4, st_pf);
            else cpcommit();                   // dummy group keeps wait depth uniform

            // S_{jt+1} into the other buffer, then P = 2^S
            const uint32_t* VpS = fsm + st_next*FL_STAGE;
            #pragma unroll
            for (int i = 0; i < 8; ++i) { sacc[cur^1][i][0] = 0u; sacc[cur^1][i][1] = 0u; }
            #pragma unroll
            for (int kc = 0; kc < 4; ++kc)
                #pragma unroll
                for (int nt = 0; nt < 8; ++nt) {
                    uint2 bb = *(const uint2*)(VpS + (nt*4 + kc)*64 + lane*2);
                    uint32_t b[2] = {bb.x, bb.y};
                    mma16h(sacc[cur^1][nt], qf[kc], b);
                }
            #pragma unroll
            for (int nt = 0; nt < 8; ++nt) {
                sacc[cur^1][nt][0] = ex2h2(sacc[cur^1][nt][0]);
                sacc[cur^1][nt][1] = ex2h2(sacc[cur^1][nt][1]);
            }
        }

        // PV_jt — independent of this iteration's S/ex2 (uses pa from last iter)
        const uint32_t* VpO = fsm + st_cur*FL_STAGE + 2048;
        #pragma unroll
        for (int kt = 0; kt < 4; ++kt) {
            uint32_t pa[4] = { sacc[cur][2*kt][0],   sacc[cur][2*kt][1],
                               sacc[cur][2*kt+1][0], sacc[cur][2*kt+1][1] };
            mma16(lsum, pa, bones);
            #pragma unroll
            for (int dg = 0; dg < 8; ++dg) {
                uint2 bb = *(const uint2*)(VpO + (kt*8 + dg)*64 + lane*2);
                uint32_t b[2] = {bb.x, bb.y};
                mma16(oacc[dg], pa, b);
            }
        }

        if (++st_cur == NSTG)  st_cur = 0;
        if (++st_next == NSTG) st_next = 0;
        if (++st_pf == NSTG)   st_pf = 0;
    }

    // ---- normalize + write O as fp16x2 ----
    int b_ = bh >> 3, h = bh & 7;
    float inv0 = 1.0f / lsum[0], inv1 = 1.0f / lsum[2];
    uint32_t* O0 = g_o16 + (((size_t)b_*SQ + (i0 + row0))*NHID + h*DD)/2;
    uint32_t* O1 = O0 + (size_t)8*(NHID/2);
    #pragma unroll
    for (int dg = 0; dg < 8; ++dg) {
        int wi = dg*4 + qd;
        O0[wi] = h2pack(oacc[dg][0]*inv0, oacc[dg][1]*inv0);
        O1[wi] = h2pack(oacc[dg][2]*inv1, oacc[dg][3]*inv1);
    }
}

// ---------------- launcher ---------------------------------------------------
extern "C" void kernel_launch(void* const* d_in, const int* in_sizes, int n_in,
                              void* d_out, int out_size) {
    const float* x  = (const float*)d_in[0];
    const float* c  = (const float*)d_in[1];
    // d_in[2..3] = Wq, bq ; d_in[4..5] = Wk, bk (UNUSED by reference) ;
    // d_in[6..7] = Wv, bv ; d_in[8..9] = Wo, bo
    const float* Wq = (const float*)d_in[2];
    const float* bq = (const float*)d_in[3];
    const float* Wv = (const float*)d_in[6];
    const float* bv = (const float*)d_in[7];
    const float* Wo = (const float*)d_in[8];
    const float* bo = (const float*)d_in[9];
    float* out = (float*)d_out;

    cudaFuncSetAttribute(proj_kernel, cudaFuncAttributeMaxDynamicSharedMemorySize,
                         GEMM_DYN_BYTES);
    cudaFuncSetAttribute(outproj_kernel, cudaFuncAttributeMaxDynamicSharedMemorySize,
                         GEMM_DYN_BYTES);
    cudaFuncSetAttribute(flash_kernel, cudaFuncAttributeMaxDynamicSharedMemorySize,
                         FLASH_DYN_BYTES);

    int prep_total = 2*NC4 + 3*NWT + NROPE;
    prep_kernel<<<(prep_total + 255)/256, 256>>>(
        (const float4*)c, (const float4*)x, Wq, Wv, Wo);
    proj_kernel<<<dim3(NHID/64, (Bb*SQ)/128, 2), 256, GEMM_DYN_BYTES>>>(bq, bv);
    packv_kernel<<<dim3(32, BH), 256>>>();
    flash_kernel<<<dim3(SQ/128, BH), 256, FLASH_DYN_BYTES>>>();
    outproj_kernel<<<dim3(CIN/64, (Bb*SQ)/128), 256, GEMM_DYN_BYTES>>>(bo, x, out);
}